// round 10
// baseline (speedup 1.0000x reference)
#include <cuda_runtime.h>
#include <cuda_bf16.h>
#include <cstdint>

// out[b] = (X X^T) X == X (X^T X);  G = X^T X is 128x128 per batch, symmetric.
// R10: syrk rebalanced into 40 blocks of 32x8 so every warp has <=144 MMAs and
// every SMSP exactly 480 (R9 critical warp had 192 -> latency tail). Reduce and
// gemm identical to R9 (measured good).

#define NB     4
#define TT     4096
#define DD     128
#define SPLITS 32
#define CHUNK  128
#define PB     136   // bf16 pitch: 272B; 272 mod 128 == 16 -> ldmatrix conflict-free

__device__ float g_partial[NB * SPLITS * DD * DD];  // 8 MB (upper blocks valid)
__device__ float g_G[NB * DD * DD];                 // 256 KB

__device__ __forceinline__ uint32_t smem_u32(const void* p) {
    uint32_t a;
    asm("{ .reg .u64 t; cvta.to.shared.u64 t, %1; cvt.u32.u64 %0, t; }" : "=r"(a) : "l"(p));
    return a;
}

__device__ __forceinline__ void ldm_x4(uint32_t* r, uint32_t addr) {
    asm volatile("ldmatrix.sync.aligned.m8n8.x4.shared.b16 {%0,%1,%2,%3}, [%4];"
                 : "=r"(r[0]), "=r"(r[1]), "=r"(r[2]), "=r"(r[3]) : "r"(addr));
}

__device__ __forceinline__ void ldm_x2(uint32_t* r, uint32_t addr) {
    asm volatile("ldmatrix.sync.aligned.m8n8.x2.shared.b16 {%0,%1}, [%2];"
                 : "=r"(r[0]), "=r"(r[1]) : "r"(addr));
}

__device__ __forceinline__ void mma_bf16(float* d, const uint32_t* a, uint32_t b0, uint32_t b1) {
    asm volatile(
        "mma.sync.aligned.m16n8k16.row.col.f32.bf16.bf16.f32 "
        "{%0,%1,%2,%3}, {%4,%5,%6,%7}, {%8,%9}, {%0,%1,%2,%3};"
        : "+f"(d[0]), "+f"(d[1]), "+f"(d[2]), "+f"(d[3])
        : "r"(a[0]), "r"(a[1]), "r"(a[2]), "r"(a[3]), "r"(b0), "r"(b1));
}

__device__ __forceinline__ void split_bf16(float v, __nv_bfloat16& h, __nv_bfloat16& l) {
    h = __float2bfloat16_rn(v);
    l = __float2bfloat16_rn(v - __bfloat162float(h));
}

// ---------------------------------------------------------------------------
// Kernel 1: upper triangle of P[b,s] = Xc^T * Xc, 40 blocks of 32x8.
// Warp -> (row-tile i, first col c0, #blocks nb), all blocks in ONE row-tile,
// column-adjacent. Per-SMSP MMA load exactly 480; critical warp 144.
//   w0-3 : i=0 nb=3 c0=24w        (cols 0..96)
//   w4-5 : i=0 nb=2 c0=96+16(w-4) (cols 96..128)
//   w6-9 : i=1 nb=3 c0=32+24(w-6) (cols 32..128)
//   w10-13: i=2 nb=2 c0=64+16(w-10)(cols 64..128)
//   w14-15: i=3 nb=2 c0=96+16(w-14)(cols 96..128)
// ---------------------------------------------------------------------------
__global__ void __launch_bounds__(512, 1)
syrk_kernel(const float* __restrict__ x)
{
    extern __shared__ char smc[];
    __nv_bfloat16* Hi = reinterpret_cast<__nv_bfloat16*>(smc);
    __nv_bfloat16* Lo = Hi + DD * PB;

    const int s = blockIdx.x, b = blockIdx.y;
    const int tid = threadIdx.x, lane = tid & 31, w = tid >> 5;

    const float4* xg = reinterpret_cast<const float4*>(
        x + ((size_t)b * TT + (size_t)s * CHUNK) * DD);

    // Transposed fill: X[t][d] -> Hi/Lo[d][t]
    {
        const int t = (w & 7) * 16 + (lane >> 1);
        const int kb = (w >> 3) * 16;
#pragma unroll
        for (int j = 0; j < 8; j++) {
            const int kq = kb + (lane & 1) + 2 * j;
            float4 v = xg[t * 32 + kq];
            float vv[4] = {v.x, v.y, v.z, v.w};
#pragma unroll
            for (int i = 0; i < 4; i++) {
                __nv_bfloat16 h, l;
                split_bf16(vv[i], h, l);
                Hi[(4 * kq + i) * PB + t] = h;
                Lo[(4 * kq + i) * PB + t] = l;
            }
        }
    }
    __syncthreads();

    // Warp job table
    int ti, c0, nb;
    if      (w < 4)  { ti = 0; nb = 3; c0 = w * 24; }
    else if (w < 6)  { ti = 0; nb = 2; c0 = 96 + (w - 4) * 16; }
    else if (w < 10) { ti = 1; nb = 3; c0 = 32 + (w - 6) * 24; }
    else if (w < 14) { ti = 2; nb = 2; c0 = 64 + (w - 10) * 16; }
    else             { ti = 3; nb = 2; c0 = 96 + (w - 14) * 16; }
    const int m0 = ti * 32;

    const int gr = lane >> 2;
    const int gc = lane & 3;

    const uint32_t hiB = smem_u32(Hi);
    const uint32_t loB = smem_u32(Lo);
    const uint32_t lrow = (uint32_t)(lane & 15);
    const uint32_t lkof = (uint32_t)((lane >> 4) << 3);
    // x2 lane mapping: lanes 0-7 -> k lo-half rows, lanes 8-15 -> k hi-half
    const uint32_t l2row = (uint32_t)(lane & 7);
    const uint32_t l2kof = (uint32_t)(((lane >> 3) & 1) << 3);

    float acc[3][2][4];
#pragma unroll
    for (int j = 0; j < 3; j++)
#pragma unroll
        for (int mt = 0; mt < 2; mt++)
#pragma unroll
            for (int q = 0; q < 4; q++) acc[j][mt][q] = 0.0f;

#pragma unroll
    for (int k0 = 0; k0 < 128; k0 += 16) {
        uint32_t ah[2][4], al[2][4];
#pragma unroll
        for (int mt = 0; mt < 2; mt++) {
            uint32_t off = (((uint32_t)(m0 + mt * 16) + lrow) * PB + (uint32_t)k0 + lkof) * 2;
            ldm_x4(ah[mt], hiB + off);
            ldm_x4(al[mt], loB + off);
        }
        // B for blocks 0,1 (16 rows at c0) — one x4 per plane
        uint32_t bh01[4], bl01[4];
        {
            uint32_t off = (((uint32_t)c0 + lrow) * PB + (uint32_t)k0 + lkof) * 2;
            ldm_x4(bh01, hiB + off);
            ldm_x4(bl01, loB + off);
        }
        // B for block 2 (8 rows at c0+16) — x2 per plane
        uint32_t bh2[2], bl2[2];
        if (nb == 3) {
            uint32_t off = (((uint32_t)(c0 + 16) + l2row) * PB + (uint32_t)k0 + l2kof) * 2;
            ldm_x2(bh2, hiB + off);
            ldm_x2(bl2, loB + off);
        }
#pragma unroll
        for (int j = 0; j < 2; j++) {
#pragma unroll
            for (int mt = 0; mt < 2; mt++) {
                mma_bf16(acc[j][mt], ah[mt], bh01[j], bh01[j + 2]);
                mma_bf16(acc[j][mt], ah[mt], bl01[j], bl01[j + 2]);
                mma_bf16(acc[j][mt], al[mt], bh01[j], bh01[j + 2]);
            }
        }
        if (nb == 3) {
#pragma unroll
            for (int mt = 0; mt < 2; mt++) {
                mma_bf16(acc[2][mt], ah[mt], bh2[0], bh2[1]);
                mma_bf16(acc[2][mt], ah[mt], bl2[0], bl2[1]);
                mma_bf16(acc[2][mt], al[mt], bh2[0], bh2[1]);
            }
        }
    }

    float* outp = g_partial + (size_t)(b * SPLITS + s) * DD * DD;
#pragma unroll
    for (int j = 0; j < 3; j++) {
        if (j < nb) {
#pragma unroll
            for (int mt = 0; mt < 2; mt++) {
                const int row = m0 + mt * 16 + gr;
                const int col = c0 + j * 8 + 2 * gc;
                *reinterpret_cast<float2*>(outp + row * DD + col) =
                    make_float2(acc[j][mt][0], acc[j][mt][1]);
                *reinterpret_cast<float2*>(outp + (row + 8) * DD + col) =
                    make_float2(acc[j][mt][2], acc[j][mt][3]);
            }
        }
    }
}

// ---------------------------------------------------------------------------
// Kernel 2: G[b] = sum_s P[b,s] (upper-only, coalesced float4) + mirror.
// One warp per (b, d1) row; lane = quad column kq. 128 CTAs x 128 threads.
// ---------------------------------------------------------------------------
__global__ void __launch_bounds__(128, 1)
reduce_kernel()
{
    const int gw  = blockIdx.x * 4 + (threadIdx.x >> 5);  // 0..511
    const int lane = threadIdx.x & 31;
    const int b   = gw >> 7;
    const int d1  = gw & 127;
    const int kq  = lane;

    if (4 * kq + 3 < d1) return;  // strictly-lower quad: produced by mirror

    const float4* base = reinterpret_cast<const float4*>(g_partial)
                       + (size_t)b * SPLITS * 4096 + d1 * 32 + kq;
    float4 acc = make_float4(0.f, 0.f, 0.f, 0.f);
#pragma unroll
    for (int s = 0; s < SPLITS; s++) {
        float4 v = base[(size_t)s * 4096];
        acc.x += v.x; acc.y += v.y; acc.z += v.z; acc.w += v.w;
    }

    float* gb = g_G + (size_t)b * 16384;
    *reinterpret_cast<float4*>(gb + d1 * 128 + 4 * kq) = acc;

    const float vv[4] = {acc.x, acc.y, acc.z, acc.w};
#pragma unroll
    for (int i = 0; i < 4; i++) {
        const int c = 4 * kq + i;
        if (c > d1) gb[c * 128 + d1] = vv[i];
    }
}

// ---------------------------------------------------------------------------
// Kernel 3: out_chunk = Xc * G[b].  A = Xc row-major; B = G row-major (symmetric).
// ---------------------------------------------------------------------------
__global__ void __launch_bounds__(512, 1)
gemm_kernel(const float* __restrict__ x, float* __restrict__ out)
{
    extern __shared__ char smc[];
    __nv_bfloat16* Ghi = reinterpret_cast<__nv_bfloat16*>(smc);
    __nv_bfloat16* Glo = Ghi + DD * PB;
    __nv_bfloat16* Xhi = Glo + DD * PB;
    __nv_bfloat16* Xlo = Xhi + DD * PB;

    const int s = blockIdx.x, b = blockIdx.y;
    const int tid = threadIdx.x, lane = tid & 31, w = tid >> 5;

    const float4* xg = reinterpret_cast<const float4*>(
        x + ((size_t)b * TT + (size_t)s * CHUNK) * DD);
    const float4* gg = reinterpret_cast<const float4*>(g_G + (size_t)b * DD * DD);

#pragma unroll
    for (int j = 0; j < 8; j++) {
        const int idx = tid + j * 512;
        const int r = idx >> 5, kq = idx & 31;
        {
            float4 v = gg[idx];
            __nv_bfloat16 hx, lx, hy, ly, hz, lz, hw, lw;
            split_bf16(v.x, hx, lx); split_bf16(v.y, hy, ly);
            split_bf16(v.z, hz, lz); split_bf16(v.w, hw, lw);
            __nv_bfloat162* dh = reinterpret_cast<__nv_bfloat162*>(Ghi + r * PB + 4 * kq);
            __nv_bfloat162* dl = reinterpret_cast<__nv_bfloat162*>(Glo + r * PB + 4 * kq);
            dh[0] = __nv_bfloat162(hx, hy); dh[1] = __nv_bfloat162(hz, hw);
            dl[0] = __nv_bfloat162(lx, ly); dl[1] = __nv_bfloat162(lz, lw);
        }
        {
            float4 v = xg[idx];
            __nv_bfloat16 hx, lx, hy, ly, hz, lz, hw, lw;
            split_bf16(v.x, hx, lx); split_bf16(v.y, hy, ly);
            split_bf16(v.z, hz, lz); split_bf16(v.w, hw, lw);
            __nv_bfloat162* dh = reinterpret_cast<__nv_bfloat162*>(Xhi + r * PB + 4 * kq);
            __nv_bfloat162* dl = reinterpret_cast<__nv_bfloat162*>(Xlo + r * PB + 4 * kq);
            dh[0] = __nv_bfloat162(hx, hy); dh[1] = __nv_bfloat162(hz, hw);
            dl[0] = __nv_bfloat162(lx, ly); dl[1] = __nv_bfloat162(lz, lw);
        }
    }
    __syncthreads();

    const int m0 = (w >> 2) * 32;
    const int n0 = (w & 3) * 32;
    const int gr = lane >> 2;
    const int gc = lane & 3;

    const uint32_t xhB = smem_u32(Xhi);
    const uint32_t xlB = smem_u32(Xlo);
    const uint32_t ghB = smem_u32(Ghi);
    const uint32_t glB = smem_u32(Glo);
    const uint32_t lrow = (uint32_t)(lane & 15);
    const uint32_t lkof = (uint32_t)((lane >> 4) << 3);

    float acc[2][4][4];
#pragma unroll
    for (int mt = 0; mt < 2; mt++)
#pragma unroll
        for (int nt = 0; nt < 4; nt++)
#pragma unroll
            for (int q = 0; q < 4; q++) acc[mt][nt][q] = 0.0f;

#pragma unroll
    for (int k0 = 0; k0 < 128; k0 += 16) {
        uint32_t ah[2][4], al[2][4], bh[2][4], bl[2][4];
#pragma unroll
        for (int mt = 0; mt < 2; mt++) {
            uint32_t off = (((uint32_t)(m0 + mt * 16) + lrow) * PB + (uint32_t)k0 + lkof) * 2;
            ldm_x4(ah[mt], xhB + off);
            ldm_x4(al[mt], xlB + off);
        }
#pragma unroll
        for (int ng = 0; ng < 2; ng++) {
            uint32_t off = (((uint32_t)(n0 + ng * 16) + lrow) * PB + (uint32_t)k0 + lkof) * 2;
            ldm_x4(bh[ng], ghB + off);
            ldm_x4(bl[ng], glB + off);
        }
#pragma unroll
        for (int ng = 0; ng < 2; ng++)
#pragma unroll
            for (int sub = 0; sub < 2; sub++) {
                const int nt = ng * 2 + sub;
#pragma unroll
                for (int mt = 0; mt < 2; mt++) {
                    mma_bf16(acc[mt][nt], ah[mt], bh[ng][sub], bh[ng][sub + 2]);
                    mma_bf16(acc[mt][nt], ah[mt], bl[ng][sub], bl[ng][sub + 2]);
                    mma_bf16(acc[mt][nt], al[mt], bh[ng][sub], bh[ng][sub + 2]);
                }
            }
    }

    float* ob = out + ((size_t)b * TT + (size_t)s * CHUNK) * DD;
#pragma unroll
    for (int mt = 0; mt < 2; mt++)
#pragma unroll
        for (int nt = 0; nt < 4; nt++) {
            const int row = m0 + mt * 16 + gr;
            const int col = n0 + nt * 8 + 2 * gc;
            *reinterpret_cast<float2*>(ob + row * DD + col) =
                make_float2(acc[mt][nt][0], acc[mt][nt][1]);
            *reinterpret_cast<float2*>(ob + (row + 8) * DD + col) =
                make_float2(acc[mt][nt][2], acc[mt][nt][3]);
        }
}

// ---------------------------------------------------------------------------

extern "C" void kernel_launch(void* const* d_in, const int* in_sizes, int n_in,
                              void* d_out, int out_size)
{
    (void)in_sizes; (void)n_in; (void)out_size;
    const float* x = (const float*)d_in[0];
    float* out = (float*)d_out;

    const int smem1 = 2 * DD * PB * 2;   // 69632 B
    const int smem3 = 4 * DD * PB * 2;   // 139264 B

    cudaFuncSetAttribute(syrk_kernel, cudaFuncAttributeMaxDynamicSharedMemorySize, smem1);
    cudaFuncSetAttribute(gemm_kernel, cudaFuncAttributeMaxDynamicSharedMemorySize, smem3);

    syrk_kernel<<<dim3(SPLITS, NB), 512, smem1>>>(x);
    reduce_kernel<<<128, 128>>>();
    gemm_kernel<<<dim3(SPLITS, NB), 512, smem3>>>(x, out);
}

// round 11
// speedup vs baseline: 1.1064x; 1.1064x over previous
#include <cuda_runtime.h>
#include <cuda_bf16.h>
#include <cstdint>

// out[b] = (X X^T) X == X (X^T X);  G = X^T X is 128x128 per batch, symmetric.
// R11: kill syrk's scalar-store transpose fill. X stays row-major [t][d] in
// smem (packed 64-bit bf16x4 stores); A/B fragments come via ldmatrix.x4.trans.
// gemm gets packed 64-bit fill stores too. Triangular syrk + R9 reduce kept.

#define NB     4
#define TT     4096
#define DD     128
#define SPLITS 32
#define CHUNK  128
#define PB     136   // bf16 pitch: 272B; 272 mod 128 == 16 -> ldmatrix conflict-free

__device__ float g_partial[NB * SPLITS * DD * DD];  // 8 MB (upper blocks valid)
__device__ float g_G[NB * DD * DD];                 // 256 KB

__device__ __forceinline__ uint32_t smem_u32(const void* p) {
    uint32_t a;
    asm("{ .reg .u64 t; cvta.to.shared.u64 t, %1; cvt.u32.u64 %0, t; }" : "=r"(a) : "l"(p));
    return a;
}

__device__ __forceinline__ void ldm_x4(uint32_t* r, uint32_t addr) {
    asm volatile("ldmatrix.sync.aligned.m8n8.x4.shared.b16 {%0,%1,%2,%3}, [%4];"
                 : "=r"(r[0]), "=r"(r[1]), "=r"(r[2]), "=r"(r[3]) : "r"(addr));
}

__device__ __forceinline__ void ldm_x4_t(uint32_t* r, uint32_t addr) {
    asm volatile("ldmatrix.sync.aligned.m8n8.x4.trans.shared.b16 {%0,%1,%2,%3}, [%4];"
                 : "=r"(r[0]), "=r"(r[1]), "=r"(r[2]), "=r"(r[3]) : "r"(addr));
}

__device__ __forceinline__ void ldm_x2_t(uint32_t* r, uint32_t addr) {
    asm volatile("ldmatrix.sync.aligned.m8n8.x2.trans.shared.b16 {%0,%1}, [%2];"
                 : "=r"(r[0]), "=r"(r[1]) : "r"(addr));
}

__device__ __forceinline__ void mma_bf16(float* d, const uint32_t* a, uint32_t b0, uint32_t b1) {
    asm volatile(
        "mma.sync.aligned.m16n8k16.row.col.f32.bf16.bf16.f32 "
        "{%0,%1,%2,%3}, {%4,%5,%6,%7}, {%8,%9}, {%0,%1,%2,%3};"
        : "+f"(d[0]), "+f"(d[1]), "+f"(d[2]), "+f"(d[3])
        : "r"(a[0]), "r"(a[1]), "r"(a[2]), "r"(a[3]), "r"(b0), "r"(b1));
}

__device__ __forceinline__ void split_bf16(float v, __nv_bfloat16& h, __nv_bfloat16& l) {
    h = __float2bfloat16_rn(v);
    l = __float2bfloat16_rn(v - __bfloat162float(h));
}

// Split a float4 into two packed bf16x4 (hi, lo) 64-bit values.
__device__ __forceinline__ void split4_pack(float4 v, uint2& hp, uint2& lp) {
    __nv_bfloat16 hx, lx, hy, ly, hz, lz, hw, lw;
    split_bf16(v.x, hx, lx); split_bf16(v.y, hy, ly);
    split_bf16(v.z, hz, lz); split_bf16(v.w, hw, lw);
    __nv_bfloat162 h01(hx, hy), h23(hz, hw), l01(lx, ly), l23(lz, lw);
    hp.x = *reinterpret_cast<uint32_t*>(&h01);
    hp.y = *reinterpret_cast<uint32_t*>(&h23);
    lp.x = *reinterpret_cast<uint32_t*>(&l01);
    lp.y = *reinterpret_cast<uint32_t*>(&l23);
}

// ---------------------------------------------------------------------------
// Kernel 1: upper triangle of P[b,s] = Xc^T * Xc, 40 blocks of 32x8.
// X kept row-major [t][d] in smem (vector fill); frags via ldmatrix.trans.
// Warp job table from R10 (per-SMSP 480 MMAs, critical warp 144).
// ---------------------------------------------------------------------------
__global__ void __launch_bounds__(512, 1)
syrk_kernel(const float* __restrict__ x)
{
    extern __shared__ char smc[];
    __nv_bfloat16* Hi = reinterpret_cast<__nv_bfloat16*>(smc);   // [128 t][PB d]
    __nv_bfloat16* Lo = Hi + DD * PB;

    const int s = blockIdx.x, b = blockIdx.y;
    const int tid = threadIdx.x, lane = tid & 31, w = tid >> 5;

    const float4* xg = reinterpret_cast<const float4*>(
        x + ((size_t)b * TT + (size_t)s * CHUNK) * DD);

    // Row-major fill: warp writes one full row per iter; 64-bit packed stores.
#pragma unroll
    for (int j = 0; j < 8; j++) {
        const int idx = tid + j * 512;        // float4 index: row t = idx>>5
        const int t = idx >> 5, kq = idx & 31;
        uint2 hp, lp;
        split4_pack(xg[idx], hp, lp);
        *reinterpret_cast<uint2*>(Hi + t * PB + 4 * kq) = hp;
        *reinterpret_cast<uint2*>(Lo + t * PB + 4 * kq) = lp;
    }
    __syncthreads();

    // Warp job table (row-tile ti, first col c0, #8-wide blocks nb)
    int ti, c0, nb;
    if      (w < 4)  { ti = 0; nb = 3; c0 = w * 24; }
    else if (w < 6)  { ti = 0; nb = 2; c0 = 96 + (w - 4) * 16; }
    else if (w < 10) { ti = 1; nb = 3; c0 = 32 + (w - 6) * 24; }
    else if (w < 14) { ti = 2; nb = 2; c0 = 64 + (w - 10) * 16; }
    else             { ti = 3; nb = 2; c0 = 96 + (w - 14) * 16; }
    const int m0 = ti * 32;

    const int gr = lane >> 2;
    const int gc = lane & 3;

    const uint32_t hiB = smem_u32(Hi);
    const uint32_t loB = smem_u32(Lo);
    // trans x4 lane map: row (k) = (lane&7) + 8*(lane>=16); col += 8 for (lane>>3)&1
    const uint32_t trow = (uint32_t)((lane & 7) + ((lane >> 4) << 3));
    const uint32_t tcol = (uint32_t)(((lane >> 3) & 1) << 3);
    // trans x2 lane map (lanes 0-15): row k = lane&15, col fixed
    const uint32_t t2row = (uint32_t)(lane & 15);

    float acc[3][2][4];
#pragma unroll
    for (int j = 0; j < 3; j++)
#pragma unroll
        for (int mt = 0; mt < 2; mt++)
#pragma unroll
            for (int q = 0; q < 4; q++) acc[j][mt][q] = 0.0f;

#pragma unroll
    for (int k0 = 0; k0 < 128; k0 += 16) {
        uint32_t ah[2][4], al[2][4];
#pragma unroll
        for (int mt = 0; mt < 2; mt++) {
            uint32_t off = (((uint32_t)k0 + trow) * PB + (uint32_t)(m0 + mt * 16) + tcol) * 2;
            ldm_x4_t(ah[mt], hiB + off);
            ldm_x4_t(al[mt], loB + off);
        }
        uint32_t bh01[4], bl01[4];
        {
            uint32_t off = (((uint32_t)k0 + trow) * PB + (uint32_t)c0 + tcol) * 2;
            ldm_x4_t(bh01, hiB + off);
            ldm_x4_t(bl01, loB + off);
        }
        uint32_t bh2[2], bl2[2];
        if (nb == 3) {
            uint32_t off = (((uint32_t)k0 + t2row) * PB + (uint32_t)(c0 + 16)) * 2;
            ldm_x2_t(bh2, hiB + off);
            ldm_x2_t(bl2, loB + off);
        }
#pragma unroll
        for (int j = 0; j < 2; j++) {
#pragma unroll
            for (int mt = 0; mt < 2; mt++) {
                mma_bf16(acc[j][mt], ah[mt], bh01[j], bh01[j + 2]);
                mma_bf16(acc[j][mt], ah[mt], bl01[j], bl01[j + 2]);
                mma_bf16(acc[j][mt], al[mt], bh01[j], bh01[j + 2]);
            }
        }
        if (nb == 3) {
#pragma unroll
            for (int mt = 0; mt < 2; mt++) {
                mma_bf16(acc[2][mt], ah[mt], bh2[0], bh2[1]);
                mma_bf16(acc[2][mt], ah[mt], bl2[0], bl2[1]);
                mma_bf16(acc[2][mt], al[mt], bh2[0], bh2[1]);
            }
        }
    }

    float* outp = g_partial + (size_t)(b * SPLITS + s) * DD * DD;
#pragma unroll
    for (int j = 0; j < 3; j++) {
        if (j < nb) {
#pragma unroll
            for (int mt = 0; mt < 2; mt++) {
                const int row = m0 + mt * 16 + gr;
                const int col = c0 + j * 8 + 2 * gc;
                *reinterpret_cast<float2*>(outp + row * DD + col) =
                    make_float2(acc[j][mt][0], acc[j][mt][1]);
                *reinterpret_cast<float2*>(outp + (row + 8) * DD + col) =
                    make_float2(acc[j][mt][2], acc[j][mt][3]);
            }
        }
    }
}

// ---------------------------------------------------------------------------
// Kernel 2: G[b] = sum_s P[b,s] (upper-only, coalesced float4) + mirror.
// ---------------------------------------------------------------------------
__global__ void __launch_bounds__(128, 1)
reduce_kernel()
{
    const int gw  = blockIdx.x * 4 + (threadIdx.x >> 5);  // 0..511
    const int lane = threadIdx.x & 31;
    const int b   = gw >> 7;
    const int d1  = gw & 127;
    const int kq  = lane;

    if (4 * kq + 3 < d1) return;

    const float4* base = reinterpret_cast<const float4*>(g_partial)
                       + (size_t)b * SPLITS * 4096 + d1 * 32 + kq;
    float4 acc = make_float4(0.f, 0.f, 0.f, 0.f);
#pragma unroll
    for (int s = 0; s < SPLITS; s++) {
        float4 v = base[(size_t)s * 4096];
        acc.x += v.x; acc.y += v.y; acc.z += v.z; acc.w += v.w;
    }

    float* gb = g_G + (size_t)b * 16384;
    *reinterpret_cast<float4*>(gb + d1 * 128 + 4 * kq) = acc;

    const float vv[4] = {acc.x, acc.y, acc.z, acc.w};
#pragma unroll
    for (int i = 0; i < 4; i++) {
        const int c = 4 * kq + i;
        if (c > d1) gb[c * 128 + d1] = vv[i];
    }
}

// ---------------------------------------------------------------------------
// Kernel 3: out_chunk = Xc * G[b].  A = Xc row-major; B = G row-major (symmetric).
// Non-trans frag loads (layouts already natural); packed 64-bit fill stores.
// ---------------------------------------------------------------------------
__global__ void __launch_bounds__(512, 1)
gemm_kernel(const float* __restrict__ x, float* __restrict__ out)
{
    extern __shared__ char smc[];
    __nv_bfloat16* Ghi = reinterpret_cast<__nv_bfloat16*>(smc);
    __nv_bfloat16* Glo = Ghi + DD * PB;
    __nv_bfloat16* Xhi = Glo + DD * PB;
    __nv_bfloat16* Xlo = Xhi + DD * PB;

    const int s = blockIdx.x, b = blockIdx.y;
    const int tid = threadIdx.x, lane = tid & 31, w = tid >> 5;

    const float4* xg = reinterpret_cast<const float4*>(
        x + ((size_t)b * TT + (size_t)s * CHUNK) * DD);
    const float4* gg = reinterpret_cast<const float4*>(g_G + (size_t)b * DD * DD);

#pragma unroll
    for (int j = 0; j < 8; j++) {
        const int idx = tid + j * 512;
        const int r = idx >> 5, kq = idx & 31;
        uint2 hp, lp;
        split4_pack(gg[idx], hp, lp);
        *reinterpret_cast<uint2*>(Ghi + r * PB + 4 * kq) = hp;
        *reinterpret_cast<uint2*>(Glo + r * PB + 4 * kq) = lp;
        split4_pack(xg[idx], hp, lp);
        *reinterpret_cast<uint2*>(Xhi + r * PB + 4 * kq) = hp;
        *reinterpret_cast<uint2*>(Xlo + r * PB + 4 * kq) = lp;
    }
    __syncthreads();

    const int m0 = (w >> 2) * 32;
    const int n0 = (w & 3) * 32;
    const int gr = lane >> 2;
    const int gc = lane & 3;

    const uint32_t xhB = smem_u32(Xhi);
    const uint32_t xlB = smem_u32(Xlo);
    const uint32_t ghB = smem_u32(Ghi);
    const uint32_t glB = smem_u32(Glo);
    const uint32_t lrow = (uint32_t)(lane & 15);
    const uint32_t lkof = (uint32_t)((lane >> 4) << 3);

    float acc[2][4][4];
#pragma unroll
    for (int mt = 0; mt < 2; mt++)
#pragma unroll
        for (int nt = 0; nt < 4; nt++)
#pragma unroll
            for (int q = 0; q < 4; q++) acc[mt][nt][q] = 0.0f;

#pragma unroll
    for (int k0 = 0; k0 < 128; k0 += 16) {
        uint32_t ah[2][4], al[2][4], bh[2][4], bl[2][4];
#pragma unroll
        for (int mt = 0; mt < 2; mt++) {
            uint32_t off = (((uint32_t)(m0 + mt * 16) + lrow) * PB + (uint32_t)k0 + lkof) * 2;
            ldm_x4(ah[mt], xhB + off);
            ldm_x4(al[mt], xlB + off);
        }
#pragma unroll
        for (int ng = 0; ng < 2; ng++) {
            uint32_t off = (((uint32_t)(n0 + ng * 16) + lrow) * PB + (uint32_t)k0 + lkof) * 2;
            ldm_x4(bh[ng], ghB + off);
            ldm_x4(bl[ng], glB + off);
        }
#pragma unroll
        for (int ng = 0; ng < 2; ng++)
#pragma unroll
            for (int sub = 0; sub < 2; sub++) {
                const int nt = ng * 2 + sub;
#pragma unroll
                for (int mt = 0; mt < 2; mt++) {
                    mma_bf16(acc[mt][nt], ah[mt], bh[ng][sub], bh[ng][sub + 2]);
                    mma_bf16(acc[mt][nt], ah[mt], bl[ng][sub], bl[ng][sub + 2]);
                    mma_bf16(acc[mt][nt], al[mt], bh[ng][sub], bh[ng][sub + 2]);
                }
            }
    }

    float* ob = out + ((size_t)b * TT + (size_t)s * CHUNK) * DD;
#pragma unroll
    for (int mt = 0; mt < 2; mt++)
#pragma unroll
        for (int nt = 0; nt < 4; nt++) {
            const int row = m0 + mt * 16 + gr;
            const int col = n0 + nt * 8 + 2 * gc;
            *reinterpret_cast<float2*>(ob + row * DD + col) =
                make_float2(acc[mt][nt][0], acc[mt][nt][1]);
            *reinterpret_cast<float2*>(ob + (row + 8) * DD + col) =
                make_float2(acc[mt][nt][2], acc[mt][nt][3]);
        }
}

// ---------------------------------------------------------------------------

extern "C" void kernel_launch(void* const* d_in, const int* in_sizes, int n_in,
                              void* d_out, int out_size)
{
    (void)in_sizes; (void)n_in; (void)out_size;
    const float* x = (const float*)d_in[0];
    float* out = (float*)d_out;

    const int smem1 = 2 * DD * PB * 2;   // 69632 B
    const int smem3 = 4 * DD * PB * 2;   // 139264 B

    cudaFuncSetAttribute(syrk_kernel, cudaFuncAttributeMaxDynamicSharedMemorySize, smem1);
    cudaFuncSetAttribute(gemm_kernel, cudaFuncAttributeMaxDynamicSharedMemorySize, smem3);

    syrk_kernel<<<dim3(SPLITS, NB), 512, smem1>>>(x);
    reduce_kernel<<<128, 128>>>();
    gemm_kernel<<<dim3(SPLITS, NB), 512, smem3>>>(x, out);
}